// round 1
// baseline (speedup 1.0000x reference)
#include <cuda_runtime.h>

// Problem constants
#define N_IMG 8
#define C_IN  64
#define HW    256
#define OC2   3

// Intermediate activation h (post conv1+bias+PReLU+fake-quant), exact fp32.
// 8*64*256*256 floats = 128 MiB device-global scratch (alloc-free workaround).
__device__ float g_h[N_IMG * C_IN * HW * HW];

// ---------------------------------------------------------------------------
// Packed f32x2 helpers (sm_100+). ptxas never auto-fuses these from C++.
// ---------------------------------------------------------------------------
__device__ __forceinline__ unsigned long long ffma2(unsigned long long a,
                                                    unsigned long long b,
                                                    unsigned long long c) {
    unsigned long long d;
    asm("fma.rn.f32x2 %0, %1, %2, %3;" : "=l"(d) : "l"(a), "l"(b), "l"(c));
    return d;
}
__device__ __forceinline__ unsigned long long pack2(float lo, float hi) {
    unsigned long long d;
    asm("mov.b64 %0, {%1, %2};" : "=l"(d) : "f"(lo), "f"(hi));
    return d;
}
__device__ __forceinline__ float2 unpack2(unsigned long long v) {
    float2 r;
    asm("mov.b64 {%0, %1}, %2;" : "=f"(r.x), "=f"(r.y) : "l"(v));
    return r;
}

// PReLU + 7-bit symmetric fake-quant (matches jnp: round half-to-even, clip [-64,63])
__device__ __forceinline__ float fq_act(float v, float a, float s) {
    v = (v >= 0.f) ? v : a * v;
    float q = rintf(v / s);
    q = fminf(fmaxf(q, -64.f), 63.f);
    return q * s;
}

// ---------------------------------------------------------------------------
// conv1: 64 -> 64, 3x3, pad 1, weight fake-quant, + bias + PReLU + act quant.
// One block per (n, output row h): 64 OC x 256 px.
// 256 threads: tid>>6 -> OC group of 16 (8 f32x2 pairs), tid&63 -> 4 px.
// ---------------------------------------------------------------------------
__global__ __launch_bounds__(256, 2)
void conv1_kernel(const float* __restrict__ x,  const float* __restrict__ w1,
                  const float* __restrict__ b1, const float* __restrict__ alpha1,
                  const float* __restrict__ sw1, const float* __restrict__ sa1)
{
    __shared__ __align__(16) float sIn[8][3][264];   // 8 cin x 3 rows x (w=-1..256, padded)
    __shared__ __align__(16) float sW[8][9][64];     // [cin][k][oc] -> oc-pairs are LDS.64

    const int h   = blockIdx.x;
    const int n   = blockIdx.y;
    const int tid = threadIdx.x;
    const int ocg = tid >> 6;          // 0..3
    const int pg  = tid & 63;          // 0..63
    const int p0  = pg << 2;           // 4 px per thread
    const int oc0 = ocg << 4;          // 16 oc per thread

    unsigned long long acc[8][4];
#pragma unroll
    for (int i = 0; i < 8; i++)
#pragma unroll
        for (int j = 0; j < 4; j++) acc[i][j] = 0ull;

    for (int c0 = 0; c0 < 64; c0 += 8) {
        if (c0) __syncthreads();
        // --- stage input tile (rows h-1..h+1, w=-1..256, zero padded) ---
        for (int i = tid; i < 8 * 3 * 264; i += 256) {
            int c = i / (3 * 264);
            int rem = i - c * (3 * 264);
            int r = rem / 264;
            int j = rem - r * 264;
            int w = j - 1, hh = h - 1 + r;
            float v = 0.f;
            if (j < 258 && (unsigned)w < 256u && (unsigned)hh < 256u)
                v = x[(((n << 6) + c0 + c) << 16) + (hh << 8) + w];
            sIn[c][r][j] = v;
        }
        // --- stage + fake-quant weights: wq = clip(rint(w/sw),-64,63)*sw ---
        for (int i = tid; i < 8 * 9 * 64; i += 256) {
            int c = i / 576;
            int rem = i - c * 576;
            int k = rem >> 6;
            int oc = rem & 63;
            float s = sw1[oc];
            float wv = w1[((oc << 6) + c0 + c) * 9 + k];
            float q = rintf(wv / s);
            q = fminf(fmaxf(q, -64.f), 63.f);
            sW[c][k][oc] = q * s;
        }
        __syncthreads();

#pragma unroll 2
        for (int c = 0; c < 8; c++) {
#pragma unroll
            for (int kh = 0; kh < 3; kh++) {
                const float* row = &sIn[c][kh][p0];
                float4 a4 = *(const float4*)row;          // 16B aligned (p0 % 4 == 0)
                float2 b2v = *(const float2*)(row + 4);
                unsigned long long xp[6];
                xp[0] = pack2(a4.x, a4.x);  xp[1] = pack2(a4.y, a4.y);
                xp[2] = pack2(a4.z, a4.z);  xp[3] = pack2(a4.w, a4.w);
                xp[4] = pack2(b2v.x, b2v.x); xp[5] = pack2(b2v.y, b2v.y);
#pragma unroll
                for (int kw = 0; kw < 3; kw++) {
                    const unsigned long long* wrow =
                        (const unsigned long long*)&sW[c][kh * 3 + kw][oc0];
#pragma unroll
                    for (int op = 0; op < 8; op++) {
                        unsigned long long wp = wrow[op];   // broadcast LDS.64, oc pair
#pragma unroll
                        for (int px = 0; px < 4; px++)
                            acc[op][px] = ffma2(wp, xp[kw + px], acc[op][px]);
                    }
                }
            }
        }
    }

    // --- epilogue: bias + PReLU + act fake-quant, coalesced float4 stores ---
#pragma unroll
    for (int op = 0; op < 8; op++) {
        float2 v0 = unpack2(acc[op][0]);
        float2 v1 = unpack2(acc[op][1]);
        float2 v2 = unpack2(acc[op][2]);
        float2 v3 = unpack2(acc[op][3]);
        int oce = oc0 + 2 * op;
        {
            float b = b1[oce], a = alpha1[oce], s = sa1[oce];
            float4 o;
            o.x = fq_act(v0.x + b, a, s); o.y = fq_act(v1.x + b, a, s);
            o.z = fq_act(v2.x + b, a, s); o.w = fq_act(v3.x + b, a, s);
            *(float4*)&g_h[(((n << 6) + oce) << 16) + (h << 8) + p0] = o;
        }
        int oco = oce + 1;
        {
            float b = b1[oco], a = alpha1[oco], s = sa1[oco];
            float4 o;
            o.x = fq_act(v0.y + b, a, s); o.y = fq_act(v1.y + b, a, s);
            o.z = fq_act(v2.y + b, a, s); o.w = fq_act(v3.y + b, a, s);
            *(float4*)&g_h[(((n << 6) + oco) << 16) + (h << 8) + p0] = o;
        }
    }
}

// ---------------------------------------------------------------------------
// conv2: 64 -> 3, 3x3, pad 1, same epilogue. ~5% of FLOPs; plain FFMA.
// One block per (n, 4 output rows). 256 threads: tid>>6 -> row, tid&63 -> 4 px.
// ---------------------------------------------------------------------------
__global__ __launch_bounds__(256)
void conv2_kernel(const float* __restrict__ w2, const float* __restrict__ b2,
                  const float* __restrict__ alpha2, const float* __restrict__ sw2,
                  const float* __restrict__ sa2, float* __restrict__ out)
{
    __shared__ __align__(16) float sIn[4][6][264];   // 4 cin x 6 rows (hb-1..hb+4)
    __shared__ float sW[4][9][3];

    const int h4 = blockIdx.x;
    const int n  = blockIdx.y;
    const int hb = h4 << 2;
    const int tid = threadIdx.x;
    const int r  = tid >> 6;           // 0..3 output row within block
    const int pg = tid & 63;
    const int p0 = pg << 2;

    float acc[3][4];
#pragma unroll
    for (int o = 0; o < 3; o++)
#pragma unroll
        for (int px = 0; px < 4; px++) acc[o][px] = 0.f;

    for (int c0 = 0; c0 < 64; c0 += 4) {
        if (c0) __syncthreads();
        for (int i = tid; i < 4 * 6 * 264; i += 256) {
            int c = i / (6 * 264);
            int rem = i - c * (6 * 264);
            int rr = rem / 264;
            int j = rem - rr * 264;
            int w = j - 1, hh = hb - 1 + rr;
            float v = 0.f;
            if (j < 258 && (unsigned)w < 256u && (unsigned)hh < 256u)
                v = g_h[(((n << 6) + c0 + c) << 16) + (hh << 8) + w];
            sIn[c][rr][j] = v;
        }
        if (tid < 4 * 9 * 3) {
            int c = tid / 27;
            int rem = tid - c * 27;
            int k = rem / 3;
            int oc = rem - k * 3;
            float s = sw2[oc];
            float wv = w2[((oc << 6) + c0 + c) * 9 + k];
            float q = rintf(wv / s);
            q = fminf(fmaxf(q, -64.f), 63.f);
            sW[c][k][oc] = q * s;
        }
        __syncthreads();

#pragma unroll
        for (int c = 0; c < 4; c++) {
#pragma unroll
            for (int kh = 0; kh < 3; kh++) {
                const float* row = &sIn[c][r + kh][p0];
                float4 a4 = *(const float4*)row;
                float2 bb = *(const float2*)(row + 4);
                float xv[6] = {a4.x, a4.y, a4.z, a4.w, bb.x, bb.y};
#pragma unroll
                for (int kw = 0; kw < 3; kw++) {
                    float w0 = sW[c][kh * 3 + kw][0];
                    float w1v = sW[c][kh * 3 + kw][1];
                    float w2v = sW[c][kh * 3 + kw][2];
#pragma unroll
                    for (int px = 0; px < 4; px++) {
                        float xvv = xv[kw + px];
                        acc[0][px] = fmaf(w0,  xvv, acc[0][px]);
                        acc[1][px] = fmaf(w1v, xvv, acc[1][px]);
                        acc[2][px] = fmaf(w2v, xvv, acc[2][px]);
                    }
                }
            }
        }
    }

#pragma unroll
    for (int o = 0; o < 3; o++) {
        float b = b2[o], a = alpha2[o], s = sa2[o];
        float4 ov;
        ov.x = fq_act(acc[o][0] + b, a, s);
        ov.y = fq_act(acc[o][1] + b, a, s);
        ov.z = fq_act(acc[o][2] + b, a, s);
        ov.w = fq_act(acc[o][3] + b, a, s);
        *(float4*)&out[((n * 3 + o) << 16) + ((hb + r) << 8) + p0] = ov;
    }
}

// ---------------------------------------------------------------------------
// Launch. Input order per metadata: x, w1, b1, w2, b2, alpha1, alpha2,
//                                   sw1, sw2, sa1, sa2. Output fp32 (8,3,256,256).
// ---------------------------------------------------------------------------
extern "C" void kernel_launch(void* const* d_in, const int* in_sizes, int n_in,
                              void* d_out, int out_size)
{
    (void)in_sizes; (void)n_in; (void)out_size;
    const float* x      = (const float*)d_in[0];
    const float* w1     = (const float*)d_in[1];
    const float* b1     = (const float*)d_in[2];
    const float* w2     = (const float*)d_in[3];
    const float* b2     = (const float*)d_in[4];
    const float* alpha1 = (const float*)d_in[5];
    const float* alpha2 = (const float*)d_in[6];
    const float* sw1    = (const float*)d_in[7];
    const float* sw2    = (const float*)d_in[8];
    const float* sa1    = (const float*)d_in[9];
    const float* sa2    = (const float*)d_in[10];

    conv1_kernel<<<dim3(HW, N_IMG), 256>>>(x, w1, b1, alpha1, sw1, sa1);
    conv2_kernel<<<dim3(HW / 4, N_IMG), 256>>>(w2, b2, alpha2, sw2, sa2, (float*)d_out);
}